// round 1
// baseline (speedup 1.0000x reference)
#include <cuda_runtime.h>

// Problem constants
static constexpr int Bc  = 2;
static constexpr int Lc  = 2048;
static constexpr int Dc  = 1024;
static constexpr int Hc  = 16;
static constexpr int HDc = 64;

// Scratch (__device__ globals: allocation-free rule)
__device__ float g_qk  [(size_t)Bc * Lc * 2 * Dc];        // [4096][2048]  q|k features
__device__ float g_S   [(size_t)Bc * Hc * Lc * Lc];       // 134M floats (536 MB) raw scores
__device__ float g_m   [Bc * Hc * Lc];                    // per (b,h,q) row max
__device__ float g_s   [Bc * Hc * Lc];                    // per (b,h,q) sumexp
__device__ float g_attn[(size_t)Bc * Lc * Lc];            // fallback attn buffer

// ---------------------------------------------------------------------------
// SGEMM: C = alpha * A @ op(B) (+ bias), 128x128 tile, 256 thr, 8x8/thread.
// BT=true : B is [N x Kd] row-major (we need B^T)
// BT=false: B is [Kd x N] row-major
// Batched via z: off = (z/zInner)*Out + (z%zInner)*In per operand.
// All dims are multiples of tile sizes (no bounds checks needed here).
// ---------------------------------------------------------------------------
template <bool BT, bool BIAS>
__global__ __launch_bounds__(256)
void sgemm_kernel(const float* __restrict__ A, int lda, long aOut, long aIn,
                  const float* __restrict__ Bm, int ldb, long bOut, long bIn,
                  float* __restrict__ C, int ldc, long cOut, long cIn,
                  int zInner, int Kd, float alpha, const float* __restrict__ bias)
{
    __shared__ float As[16][128];
    __shared__ float Bs[16][128];

    int z  = blockIdx.z;
    int zo = z / zInner, zi = z % zInner;
    A  += (long)zo * aOut + (long)zi * aIn;
    Bm += (long)zo * bOut + (long)zi * bIn;
    C  += (long)zo * cOut + (long)zi * cIn;

    const int m0 = blockIdx.y * 128;
    const int n0 = blockIdx.x * 128;
    const int tid = threadIdx.x;
    const int tm = tid >> 4;      // 0..15
    const int tn = tid & 15;      // 0..15

    const int lrow = tid >> 2;    // 0..63
    const int lq   = tid & 3;     // 0..3 (float4 along K)

    float acc[8][8];
#pragma unroll
    for (int i = 0; i < 8; i++)
#pragma unroll
        for (int j = 0; j < 8; j++) acc[i][j] = 0.0f;

    for (int k0 = 0; k0 < Kd; k0 += 16) {
        // --- load A tile (transpose into As[k][m]) ---
#pragma unroll
        for (int half = 0; half < 2; half++) {
            int r = lrow + half * 64;
            float4 v = *(const float4*)&A[(long)(m0 + r) * lda + k0 + 4 * lq];
            As[4 * lq + 0][r] = v.x;
            As[4 * lq + 1][r] = v.y;
            As[4 * lq + 2][r] = v.z;
            As[4 * lq + 3][r] = v.w;
        }
        // --- load B tile into Bs[k][n] ---
        if (BT) {
#pragma unroll
            for (int half = 0; half < 2; half++) {
                int r = lrow + half * 64;
                float4 v = *(const float4*)&Bm[(long)(n0 + r) * ldb + k0 + 4 * lq];
                Bs[4 * lq + 0][r] = v.x;
                Bs[4 * lq + 1][r] = v.y;
                Bs[4 * lq + 2][r] = v.z;
                Bs[4 * lq + 3][r] = v.w;
            }
        } else {
#pragma unroll
            for (int j = 0; j < 2; j++) {
                int i4  = tid + 256 * j;      // 0..511 float4 slots
                int row = i4 >> 5;            // 0..15
                int c4  = i4 & 31;            // 0..31
                float4 v = *(const float4*)&Bm[(long)(k0 + row) * ldb + n0 + 4 * c4];
                *(float4*)&Bs[row][4 * c4] = v;
            }
        }
        __syncthreads();

#pragma unroll
        for (int kk = 0; kk < 16; kk++) {
            float a[8], b[8];
#pragma unroll
            for (int i = 0; i < 8; i++) a[i] = As[kk][tm * 8 + i];
#pragma unroll
            for (int j = 0; j < 8; j++) b[j] = Bs[kk][tn * 8 + j];
#pragma unroll
            for (int i = 0; i < 8; i++)
#pragma unroll
                for (int j = 0; j < 8; j++) acc[i][j] += a[i] * b[j];
        }
        __syncthreads();
    }

    // epilogue
#pragma unroll
    for (int i = 0; i < 8; i++) {
        int m = m0 + tm * 8 + i;
#pragma unroll
        for (int j = 0; j < 8; j += 4) {
            int n = n0 + tn * 8 + j;
            float4 v;
            v.x = acc[i][j + 0] * alpha;
            v.y = acc[i][j + 1] * alpha;
            v.z = acc[i][j + 2] * alpha;
            v.w = acc[i][j + 3] * alpha;
            if (BIAS) {
                float4 bb = *(const float4*)&bias[n];
                v.x += bb.x; v.y += bb.y; v.z += bb.z; v.w += bb.w;
            }
            *(float4*)&C[(long)m * ldc + n] = v;
        }
    }
}

// ---------------------------------------------------------------------------
// Per-(b,h,q) row: max and sumexp over the 2048 scores. 8 warps/block, 1 row/warp.
// ---------------------------------------------------------------------------
__global__ __launch_bounds__(256)
void rowstat_kernel(const float* __restrict__ S, float* __restrict__ gm,
                    float* __restrict__ gs)
{
    int row  = blockIdx.x * 8 + (threadIdx.x >> 5);
    int lane = threadIdx.x & 31;
    const float* r = S + (long)row * Lc;

    float m = -1e30f;
    for (int j = lane; j < Lc; j += 32) m = fmaxf(m, r[j]);
#pragma unroll
    for (int o = 16; o; o >>= 1) m = fmaxf(m, __shfl_xor_sync(0xFFFFFFFFu, m, o));

    float s = 0.0f;
    for (int j = lane; j < Lc; j += 32) s += __expf(r[j] - m);
#pragma unroll
    for (int o = 16; o; o >>= 1) s += __shfl_xor_sync(0xFFFFFFFFu, s, o);

    if (lane == 0) { gm[row] = m; gs[row] = s; }
}

// ---------------------------------------------------------------------------
// Per (b,q): head-mean of softmax, temporal decay, renormalize. 1 block/row.
// ---------------------------------------------------------------------------
__global__ __launch_bounds__(256)
void attn_kernel(const float* __restrict__ S, const float* __restrict__ gm,
                 const float* __restrict__ gs, const float* __restrict__ td,
                 float* __restrict__ attn)
{
    const int bq = blockIdx.x;            // 0..4095
    const int b  = bq >> 11;
    const int q  = bq & (Lc - 1);
    const int tid = threadIdx.x;

    __shared__ float wrow[Lc];
    __shared__ float mh[Hc], ish[Hc];
    __shared__ float red[8];

    if (tid < Hc) {
        int idx = (b * Hc + tid) * Lc + q;
        mh[tid]  = gm[idx];
        ish[tid] = 1.0f / gs[idx];        // gs >= 1 always
    }
    __syncthreads();

    const float* tdr = td + (long)bq * Lc;
    float lsum = 0.0f;
#pragma unroll
    for (int it = 0; it < Lc / 256; it++) {
        int k = tid + it * 256;
        float acc = 0.0f;
#pragma unroll
        for (int h = 0; h < Hc; h++) {
            long off = ((long)((b * Hc + h) * Lc + q)) * Lc + k;
            acc += __expf(S[off] - mh[h]) * ish[h];
        }
        float w = acc * (1.0f / (float)Hc) * __expf(-0.1f * tdr[k]);
        wrow[k] = w;
        lsum += w;
    }
#pragma unroll
    for (int o = 16; o; o >>= 1) lsum += __shfl_xor_sync(0xFFFFFFFFu, lsum, o);
    if ((tid & 31) == 0) red[tid >> 5] = lsum;
    __syncthreads();
    if (tid == 0) {
        float t = 0.0f;
#pragma unroll
        for (int i = 0; i < 8; i++) t += red[i];
        red[0] = 1.0f / (t + 1e-8f);
    }
    __syncthreads();
    const float inv = red[0];

#pragma unroll
    for (int it = 0; it < Lc / 256; it++) {
        int k = tid + it * 256;
        attn[(long)bq * Lc + k] = wrow[k] * inv;
    }
}

// ---------------------------------------------------------------------------
extern "C" void kernel_launch(void* const* d_in, const int* in_sizes, int n_in,
                              void* d_out, int out_size)
{
    const float* x    = (const float*)d_in[0];   // [B,L,D]
    const float* td   = (const float*)d_in[1];   // [B,L,L]
    const float* W    = (const float*)d_in[2];   // [3D,D]
    const float* bias = (const float*)d_in[3];   // [3D]
    float* out = (float*)d_out;

    float *qk, *S, *gm, *gs, *attn_scratch;
    cudaGetSymbolAddress((void**)&qk, g_qk);
    cudaGetSymbolAddress((void**)&S, g_S);
    cudaGetSymbolAddress((void**)&gm, g_m);
    cudaGetSymbolAddress((void**)&gs, g_s);
    cudaGetSymbolAddress((void**)&attn_scratch, g_attn);

    const long outElems  = (long)Bc * Lc * Dc;   // 4,194,304
    const long attnElems = (long)Bc * Lc * Lc;   // 8,388,608

    float* out_o = out;
    float* out_a = ((long)out_size >= outElems + attnElems) ? (out + outElems)
                                                            : attn_scratch;

    // K1: qk = x @ W[:2048,:]^T + bias   (v projection is dead — skipped)
    {
        dim3 grid(2 * Dc / 128, (Bc * Lc) / 128, 1);   // (16,32,1)
        sgemm_kernel<true, true><<<grid, 256>>>(
            x, Dc, 0, 0,
            W, Dc, 0, 0,
            qk, 2 * Dc, 0, 0,
            1, Dc, 1.0f, bias);
    }

    // K2: S[b,h] = 0.125 * Q(b,h) @ K(b,h)^T ; z = b*16+h
    {
        dim3 grid(Lc / 128, Lc / 128, Bc * Hc);        // (16,16,32)
        sgemm_kernel<true, false><<<grid, 256>>>(
            qk,          2 * Dc, (long)Lc * 2 * Dc, HDc,
            qk + Dc,     2 * Dc, (long)Lc * 2 * Dc, HDc,
            S,           Lc,     (long)Hc * Lc * Lc, (long)Lc * Lc,
            Hc, HDc, 0.125f, nullptr);
    }

    // K3: per-row max/sumexp
    rowstat_kernel<<<(Bc * Hc * Lc) / 8, 256>>>(S, gm, gs);

    // K4: head-mean softmax + decay + renormalize -> attn
    attn_kernel<<<Bc * Lc, 256>>>(S, gm, gs, td, out_a);

    // K5: output = attn @ x  (per batch)
    {
        dim3 grid(Dc / 128, Lc / 128, Bc);             // (8,16,2)
        sgemm_kernel<false, false><<<grid, 256>>>(
            out_a, Lc, (long)Lc * Lc, 0,
            x,     Dc, (long)Lc * Dc, 0,
            out_o, Dc, (long)Lc * Dc, 0,
            1, Lc, 1.0f, nullptr);
    }
}

// round 3
// speedup vs baseline: 1.3827x; 1.3827x over previous
#include <cuda_runtime.h>
#include <cstdint>

// Problem constants
static constexpr int Bc  = 2;
static constexpr int Lc  = 2048;
static constexpr int Dc  = 1024;
static constexpr int Hc  = 16;

// Scratch (__device__ globals: allocation-free rule)
__device__ float g_qk   [(size_t)Bc * Lc * 2 * Dc];     // [4096][2048] q|k features
__device__ float g_S    [(size_t)Bc * Hc * Lc * Lc];    // exp(scores)  (536 MB)
__device__ float g_xT   [(size_t)Bc * Dc * Lc];         // x transposed [b][d][l]
__device__ float g_part [(size_t)Bc * Hc * 16 * Lc];    // per-ntile row sums
__device__ float g_gs   [Bc * Hc * Lc];                 // per (b,h,q) sumexp
__device__ float g_attn [(size_t)Bc * Lc * Lc];         // fallback attn buffer

// ---------------------------------------------------------------------------
// Helpers (all plain sm_80-class PTX — no 'a' features, compiles for sm_103)
// ---------------------------------------------------------------------------
__device__ __forceinline__ uint32_t smem_u32(const void* p) {
    uint32_t a;
    asm("{ .reg .u64 t; cvta.to.shared.u64 t, %1; cvt.u32.u64 %0, t; }" : "=r"(a) : "l"(p));
    return a;
}
__device__ __forceinline__ void split_tf32(float x, uint32_t& hi, uint32_t& lo) {
    uint32_t h;
    asm("cvt.rna.tf32.f32 %0, %1;" : "=r"(h) : "f"(x));
    float l = x - __uint_as_float(h);
    uint32_t l2;
    asm("cvt.rna.tf32.f32 %0, %1;" : "=r"(l2) : "f"(l));
    hi = h; lo = l2;
}
__device__ __forceinline__ void mma8(float* c, const uint32_t* a, const uint32_t* b) {
    asm volatile(
        "mma.sync.aligned.m16n8k8.row.col.f32.tf32.tf32.f32 "
        "{%0,%1,%2,%3}, {%4,%5,%6,%7}, {%8,%9}, {%0,%1,%2,%3};"
        : "+f"(c[0]), "+f"(c[1]), "+f"(c[2]), "+f"(c[3])
        : "r"(a[0]), "r"(a[1]), "r"(a[2]), "r"(a[3]), "r"(b[0]), "r"(b[1]));
}
__device__ __forceinline__ void cp_async16(uint32_t dst, const void* src) {
    asm volatile("cp.async.cg.shared.global [%0], [%1], 16;" :: "r"(dst), "l"(src));
}
#define CP_COMMIT() asm volatile("cp.async.commit_group;" ::: "memory")
#define CP_WAIT(N)  asm volatile("cp.async.wait_group %0;" :: "n"(N) : "memory")

// ---------------------------------------------------------------------------
// 3xTF32 warp-MMA GEMM: C[128x128 tile/blk] = alpha * A @ B^T  (A,B K-major f32)
// EPI: 0 = plain store, 1 = +bias, 2 = exp(v) store + per-row partial sums
// 256 thr = 8 warps as 4(m) x 2(n); warp tile 32x64; mma m16n8k8 tf32, 3x split.
// SMEM: 2 stages x (A[128][36] + B[128][36] f32) = 72KB; epilogue staging reuses.
// ---------------------------------------------------------------------------
static constexpr int PADK  = 36;                       // 32 + 4 pad (LDS conflict-free)
static constexpr int AB_FLOATS = 128 * PADK;           // per matrix per stage
static constexpr int STAGE_FLOATS = 2 * AB_FLOATS;     // A then B
static constexpr int SMEM_GEMM_BYTES = 2 * STAGE_FLOATS * 4;  // 73728

template <int EPI>
__global__ __launch_bounds__(256, 2)
void gemm_tc(const float* __restrict__ A, int lda, long aOut, long aIn,
             const float* __restrict__ B, int ldb, long bOut, long bIn,
             float* __restrict__ C, int ldc, long cOut, long cIn,
             int zInner, int Kd, float alpha,
             const float* __restrict__ bias, float* __restrict__ partial)
{
    extern __shared__ __align__(16) float smem[];
    const uint32_t sb = smem_u32(smem);

    const int tid  = threadIdx.x;
    const int wid  = tid >> 5;
    const int lane = tid & 31;
    const int wm   = wid >> 1;          // 0..3
    const int wn   = wid & 1;           // 0..1
    const int lq   = lane >> 2;         // 0..7
    const int lr   = lane & 3;          // 0..3

    const int z  = blockIdx.z;
    const int zo = z / zInner, zi = z % zInner;
    A += (long)zo * aOut + (long)zi * aIn;
    B += (long)zo * bOut + (long)zi * bIn;
    C += (long)zo * cOut + (long)zi * cIn;

    const int m0 = blockIdx.y * 128;
    const int n0 = blockIdx.x * 128;

    float acc[2][8][4];
#pragma unroll
    for (int mt = 0; mt < 2; mt++)
#pragma unroll
        for (int nt = 0; nt < 8; nt++)
#pragma unroll
            for (int i = 0; i < 4; i++) acc[mt][nt][i] = 0.0f;

    const int nc = Kd / 32;

    // async copy of one 128x32 chunk pair into stage s
    auto preload = [&](int c, int s) {
        const int k0 = c * 32;
        const uint32_t abase = sb + (uint32_t)(s * STAGE_FLOATS) * 4;
        const uint32_t bbase = abase + (uint32_t)AB_FLOATS * 4;
#pragma unroll
        for (int j = 0; j < 4; j++) {
            const int f   = j * 256 + tid;
            const int row = f >> 3;
            const int c4  = f & 7;
            const uint32_t off = (uint32_t)(row * PADK + c4 * 4) * 4;
            cp_async16(abase + off, &A[(size_t)(m0 + row) * lda + k0 + c4 * 4]);
            cp_async16(bbase + off, &B[(size_t)(n0 + row) * ldb + k0 + c4 * 4]);
        }
    };

    preload(0, 0);
    CP_COMMIT();

    for (int c = 0; c < nc; c++) {
        const int s = c & 1;
        if (c + 1 < nc) {
            preload(c + 1, s ^ 1);
            CP_COMMIT();
            CP_WAIT(1);
        } else {
            CP_WAIT(0);
        }
        __syncthreads();

        const float* As = smem + s * STAGE_FLOATS;
        const float* Bs = As + AB_FLOATS;

#pragma unroll
        for (int ks = 0; ks < 4; ks++) {
            // A fragments (2 m-tiles), split into hi/lo tf32
            uint32_t ahi[2][4], alo[2][4];
#pragma unroll
            for (int mt = 0; mt < 2; mt++) {
                const int r = wm * 32 + mt * 16 + lq;
                const int cI = ks * 8 + lr;
                split_tf32(As[(r    ) * PADK + cI    ], ahi[mt][0], alo[mt][0]);
                split_tf32(As[(r + 8) * PADK + cI    ], ahi[mt][1], alo[mt][1]);
                split_tf32(As[(r    ) * PADK + cI + 4], ahi[mt][2], alo[mt][2]);
                split_tf32(As[(r + 8) * PADK + cI + 4], ahi[mt][3], alo[mt][3]);
            }
#pragma unroll
            for (int nt = 0; nt < 8; nt++) {
                const int n  = wn * 64 + nt * 8 + lq;
                const int cI = ks * 8 + lr;
                uint32_t bhi[2], blo[2];
                split_tf32(Bs[n * PADK + cI    ], bhi[0], blo[0]);
                split_tf32(Bs[n * PADK + cI + 4], bhi[1], blo[1]);
                mma8(acc[0][nt], ahi[0], bhi);
                mma8(acc[1][nt], ahi[1], bhi);
                mma8(acc[0][nt], ahi[0], blo);
                mma8(acc[1][nt], ahi[1], blo);
                mma8(acc[0][nt], alo[0], bhi);
                mma8(acc[1][nt], alo[1], bhi);
            }
        }
        __syncthreads();
    }

    // ---- epilogue: regs -> staged smem (alpha, exp) -> coalesced GMEM ----
    float* stg = smem;                                // 128 x 132 floats
#pragma unroll
    for (int mt = 0; mt < 2; mt++) {
        const int r = wm * 32 + mt * 16 + lq;
#pragma unroll
        for (int nt = 0; nt < 8; nt++) {
            const int cI = wn * 64 + nt * 8 + 2 * lr;
            float v0 = acc[mt][nt][0] * alpha;
            float v1 = acc[mt][nt][1] * alpha;
            float v2 = acc[mt][nt][2] * alpha;
            float v3 = acc[mt][nt][3] * alpha;
            if (EPI == 2) {
                v0 = __expf(v0); v1 = __expf(v1);
                v2 = __expf(v2); v3 = __expf(v3);
            }
            *(float2*)&stg[(r    ) * 132 + cI] = make_float2(v0, v1);
            *(float2*)&stg[(r + 8) * 132 + cI] = make_float2(v2, v3);
        }
    }
    __syncthreads();

    if (EPI == 2) {
        // per-row partial sums over this block's 128 cols
        const int row  = tid >> 1;
        const int half = tid & 1;
        float s = 0.0f;
#pragma unroll
        for (int j4 = 0; j4 < 16; j4++) {
            float4 v = *(const float4*)&stg[row * 132 + half * 64 + j4 * 4];
            s += v.x + v.y + v.z + v.w;
        }
        s += __shfl_xor_sync(0xFFFFFFFFu, s, 1);
        if (half == 0)
            partial[(size_t)(z * 16 + blockIdx.x) * Lc + m0 + row] = s;
    }

    float4 bv = make_float4(0.f, 0.f, 0.f, 0.f);
    if (EPI == 1) bv = *(const float4*)&bias[n0 + lane * 4];
#pragma unroll
    for (int it = 0; it < 16; it++) {
        const int r2 = it * 8 + wid;
        float4 v = *(const float4*)&stg[r2 * 132 + lane * 4];
        if (EPI == 1) { v.x += bv.x; v.y += bv.y; v.z += bv.z; v.w += bv.w; }
        *(float4*)&C[(size_t)(m0 + r2) * ldc + n0 + lane * 4] = v;
    }
}

// ---------------------------------------------------------------------------
// x [B,L,D] -> xT [B,D,L]
// ---------------------------------------------------------------------------
__global__ __launch_bounds__(256)
void transpose_kernel(const float* __restrict__ x, float* __restrict__ xT)
{
    __shared__ float t[32][33];
    const int b  = blockIdx.z;
    const int l0 = blockIdx.y * 32;
    const int d0 = blockIdx.x * 32;
    const int tx = threadIdx.x, ty = threadIdx.y;
#pragma unroll
    for (int j = 0; j < 4; j++)
        t[ty + 8 * j][tx] = x[(size_t)b * Lc * Dc + (size_t)(l0 + ty + 8 * j) * Dc + d0 + tx];
    __syncthreads();
#pragma unroll
    for (int j = 0; j < 4; j++)
        xT[(size_t)b * Dc * Lc + (size_t)(d0 + ty + 8 * j) * Lc + l0 + tx] = t[tx][ty + 8 * j];
}

// ---------------------------------------------------------------------------
// gs[z][q] = sum over 16 n-tiles of partial sums
// ---------------------------------------------------------------------------
__global__ __launch_bounds__(256)
void reduce_gs_kernel(const float* __restrict__ partial, float* __restrict__ gs)
{
    const int i = blockIdx.x * 256 + threadIdx.x;    // z*2048 + q
    const int z = i >> 11, q = i & (Lc - 1);
    float s = 0.0f;
#pragma unroll
    for (int kt = 0; kt < 16; kt++)
        s += partial[(size_t)(z * 16 + kt) * Lc + q];
    gs[i] = s;
}

// ---------------------------------------------------------------------------
// Per (b,q): head-mean of exp-scores, temporal decay, renormalize.
// ---------------------------------------------------------------------------
__global__ __launch_bounds__(256)
void attn_kernel(const float* __restrict__ E, const float* __restrict__ gs,
                 const float* __restrict__ td, float* __restrict__ attn)
{
    const int bq = blockIdx.x;            // 0..4095
    const int b  = bq >> 11;
    const int q  = bq & (Lc - 1);
    const int tid = threadIdx.x;

    __shared__ float wrow[Lc];
    __shared__ float ish[Hc];
    __shared__ float red[8];

    if (tid < Hc)
        ish[tid] = 1.0f / (16.0f * gs[(b * Hc + tid) * Lc + q]);
    __syncthreads();

    const float4* tdr = (const float4*)(td + (size_t)bq * Lc);
    float lsum = 0.0f;
#pragma unroll
    for (int it = 0; it < Lc / 1024; it++) {
        const int k4 = tid + it * 256;
        float4 acc = make_float4(0.f, 0.f, 0.f, 0.f);
#pragma unroll
        for (int h = 0; h < Hc; h++) {
            const float4 e = *(const float4*)&E[((size_t)(b * Hc + h) * Lc + q) * Lc + 4 * k4];
            const float is = ish[h];
            acc.x += e.x * is; acc.y += e.y * is;
            acc.z += e.z * is; acc.w += e.w * is;
        }
        const float4 t = tdr[k4];
        float4 w;
        w.x = acc.x * __expf(-0.1f * t.x);
        w.y = acc.y * __expf(-0.1f * t.y);
        w.z = acc.z * __expf(-0.1f * t.z);
        w.w = acc.w * __expf(-0.1f * t.w);
        *(float4*)&wrow[4 * k4] = w;
        lsum += w.x + w.y + w.z + w.w;
    }
#pragma unroll
    for (int o = 16; o; o >>= 1) lsum += __shfl_xor_sync(0xFFFFFFFFu, lsum, o);
    if ((tid & 31) == 0) red[tid >> 5] = lsum;
    __syncthreads();
    if (tid == 0) {
        float t = 0.0f;
#pragma unroll
        for (int i = 0; i < 8; i++) t += red[i];
        red[0] = 1.0f / (t + 1e-8f);
    }
    __syncthreads();
    const float inv = red[0];

#pragma unroll
    for (int it = 0; it < Lc / 1024; it++) {
        const int k4 = tid + it * 256;
        float4 w = *(const float4*)&wrow[4 * k4];
        w.x *= inv; w.y *= inv; w.z *= inv; w.w *= inv;
        *(float4*)&attn[(size_t)bq * Lc + 4 * k4] = w;
    }
}

// ---------------------------------------------------------------------------
extern "C" void kernel_launch(void* const* d_in, const int* in_sizes, int n_in,
                              void* d_out, int out_size)
{
    const float* x    = (const float*)d_in[0];   // [B,L,D]
    const float* td   = (const float*)d_in[1];   // [B,L,L]
    const float* W    = (const float*)d_in[2];   // [3D,D]
    const float* bias = (const float*)d_in[3];   // [3D]
    float* out = (float*)d_out;

    float *qk, *S, *xT, *part, *gs, *attn_scratch;
    cudaGetSymbolAddress((void**)&qk, g_qk);
    cudaGetSymbolAddress((void**)&S, g_S);
    cudaGetSymbolAddress((void**)&xT, g_xT);
    cudaGetSymbolAddress((void**)&part, g_part);
    cudaGetSymbolAddress((void**)&gs, g_gs);
    cudaGetSymbolAddress((void**)&attn_scratch, g_attn);

    cudaFuncSetAttribute(gemm_tc<0>, cudaFuncAttributeMaxDynamicSharedMemorySize, SMEM_GEMM_BYTES);
    cudaFuncSetAttribute(gemm_tc<1>, cudaFuncAttributeMaxDynamicSharedMemorySize, SMEM_GEMM_BYTES);
    cudaFuncSetAttribute(gemm_tc<2>, cudaFuncAttributeMaxDynamicSharedMemorySize, SMEM_GEMM_BYTES);

    const long outElems  = (long)Bc * Lc * Dc;   // 4,194,304
    const long attnElems = (long)Bc * Lc * Lc;   // 8,388,608
    float* out_o = out;
    float* out_a = ((long)out_size >= outElems + attnElems) ? (out + outElems)
                                                            : attn_scratch;

    // T: xT[b][d][l] = x[b][l][d]
    {
        dim3 grid(Dc / 32, Lc / 32, Bc);
        transpose_kernel<<<grid, dim3(32, 8)>>>(x, xT);
    }

    // K1: qk = x @ W[:2048,:]^T + bias   (v projection dead — skipped)
    {
        dim3 grid(2 * Dc / 128, (Bc * Lc) / 128, 1);   // (16,32,1)
        gemm_tc<1><<<grid, 256, SMEM_GEMM_BYTES>>>(
            x, Dc, 0, 0,
            W, Dc, 0, 0,
            qk, 2 * Dc, 0, 0,
            1, Dc, 1.0f, bias, nullptr);
    }

    // K2: S[b,h] = exp(0.125 * Q @ K^T), fused per-row partial sums
    {
        dim3 grid(Lc / 128, Lc / 128, Bc * Hc);        // (16,16,32)
        gemm_tc<2><<<grid, 256, SMEM_GEMM_BYTES>>>(
            qk,       2 * Dc, (long)Lc * 2 * Dc, 64,
            qk + Dc,  2 * Dc, (long)Lc * 2 * Dc, 64,
            S,        Lc,     (long)Hc * Lc * Lc, (long)Lc * Lc,
            Hc, 64, 0.125f, nullptr, part);
    }

    // K3: gs = sum of partials
    reduce_gs_kernel<<<(Bc * Hc * Lc) / 256, 256>>>(part, gs);

    // K4: head-mean + decay + renormalize -> attn
    attn_kernel<<<Bc * Lc, 256>>>(S, gs, td, out_a);

    // K5: output = attn @ x   (B operand = xT, K-major)
    {
        dim3 grid(Dc / 128, Lc / 128, Bc);             // (8,16,2)
        gemm_tc<0><<<grid, 256, SMEM_GEMM_BYTES>>>(
            out_a, Lc, (long)Lc * Lc, 0,
            xT,    Lc, (long)Dc * Lc, 0,
            out_o, Dc, (long)Lc * Dc, 0,
            1, Lc, 1.0f, nullptr, nullptr);
    }
}

// round 4
// speedup vs baseline: 3.0200x; 2.1840x over previous
#include <cuda_runtime.h>
#include <cuda_fp16.h>
#include <cstdint>

// Problem constants
static constexpr int Bc  = 2;
static constexpr int Lc  = 2048;
static constexpr int Dc  = 1024;
static constexpr int Hc  = 16;

// Scratch (__device__ globals: allocation-free rule)
__device__ float  g_qk  [(size_t)Bc * Lc * 2 * Dc];     // [4096][2048] q|k (tf32-rounded)
__device__ __half g_S   [(size_t)Bc * Hc * Lc * Lc];    // exp(score-6) fp16 (268 MB)
__device__ float  g_xT  [(size_t)Bc * Dc * Lc];         // x^T, tf32-rounded
__device__ float  g_xR  [(size_t)Bc * Lc * Dc];         // x, tf32-rounded
__device__ float  g_WR  [(size_t)2 * Dc * Dc];          // W[:2048], tf32-rounded
__device__ float  g_part[(size_t)Bc * Hc * 16 * Lc];    // per-ntile row sums
__device__ float  g_gs  [Bc * Hc * Lc];                 // per (b,h,q) sumexp
__device__ float  g_attn[(size_t)Bc * Lc * Lc];         // fallback attn buffer

// ---------------------------------------------------------------------------
__device__ __forceinline__ uint32_t smem_u32(const void* p) {
    uint32_t a;
    asm("{ .reg .u64 t; cvta.to.shared.u64 t, %1; cvt.u32.u64 %0, t; }" : "=r"(a) : "l"(p));
    return a;
}
__device__ __forceinline__ uint32_t f2tf(float x) {
    uint32_t r;
    asm("cvt.rna.tf32.f32 %0, %1;" : "=r"(r) : "f"(x));
    return r;
}
__device__ __forceinline__ float roundtf(float x) { return __uint_as_float(f2tf(x)); }

__device__ __forceinline__ void mma8(float* c, const uint32_t* a, const uint32_t* b) {
    asm volatile(
        "mma.sync.aligned.m16n8k8.row.col.f32.tf32.tf32.f32 "
        "{%0,%1,%2,%3}, {%4,%5,%6,%7}, {%8,%9}, {%0,%1,%2,%3};"
        : "+f"(c[0]), "+f"(c[1]), "+f"(c[2]), "+f"(c[3])
        : "r"(a[0]), "r"(a[1]), "r"(a[2]), "r"(a[3]), "r"(b[0]), "r"(b[1]));
}
__device__ __forceinline__ void cp_async16(uint32_t dst, const void* src) {
    asm volatile("cp.async.cg.shared.global [%0], [%1], 16;" :: "r"(dst), "l"(src));
}
#define CP_COMMIT() asm volatile("cp.async.commit_group;" ::: "memory")
#define CP_WAIT(N)  asm volatile("cp.async.wait_group %0;" :: "n"(N) : "memory")

// ---------------------------------------------------------------------------
// Single-TF32 warp-MMA GEMM: C[128x128/blk] = f(alpha * A @ B^T)
// EPI: 0 = plain fp32, 1 = +bias then tf32-round, 2 = exp(v-6)->fp16 + row sums
// CVTA: convert A operand to tf32 in-register (else operands pre-rounded)
// 256 thr = 8 warps (4m x 2n), warp tile 32x64, mma m16n8k8.
// ---------------------------------------------------------------------------
static constexpr int PADK  = 36;
static constexpr int AB_FLOATS = 128 * PADK;
static constexpr int STAGE_FLOATS = 2 * AB_FLOATS;
static constexpr int SMEM_GEMM_BYTES = 2 * STAGE_FLOATS * 4;   // 73728

template <int EPI, bool CVTA, typename CT>
__global__ __launch_bounds__(256, 2)
void gemm_tc(const float* __restrict__ A, int lda, long aOut, long aIn,
             const float* __restrict__ B, int ldb, long bOut, long bIn,
             CT* __restrict__ C, int ldc, long cOut, long cIn,
             int zInner, int Kd, float alpha,
             const float* __restrict__ bias, float* __restrict__ partial)
{
    extern __shared__ __align__(16) float smem[];
    const uint32_t sb = smem_u32(smem);

    const int tid  = threadIdx.x;
    const int wid  = tid >> 5;
    const int lane = tid & 31;
    const int wm   = wid >> 1;
    const int wn   = wid & 1;
    const int lq   = lane >> 2;
    const int lr   = lane & 3;

    const int z  = blockIdx.z;
    const int zo = z / zInner, zi = z % zInner;
    A += (long)zo * aOut + (long)zi * aIn;
    B += (long)zo * bOut + (long)zi * bIn;
    C += (long)zo * cOut + (long)zi * cIn;

    const int m0 = blockIdx.y * 128;
    const int n0 = blockIdx.x * 128;

    float acc[2][8][4];
#pragma unroll
    for (int mt = 0; mt < 2; mt++)
#pragma unroll
        for (int nt = 0; nt < 8; nt++)
#pragma unroll
            for (int i = 0; i < 4; i++) acc[mt][nt][i] = 0.0f;

    const int nc = Kd / 32;

    auto preload = [&](int c, int s) {
        const int k0 = c * 32;
        const uint32_t abase = sb + (uint32_t)(s * STAGE_FLOATS) * 4;
        const uint32_t bbase = abase + (uint32_t)AB_FLOATS * 4;
#pragma unroll
        for (int j = 0; j < 4; j++) {
            const int f   = j * 256 + tid;
            const int row = f >> 3;
            const int c4  = f & 7;
            const uint32_t off = (uint32_t)(row * PADK + c4 * 4) * 4;
            cp_async16(abase + off, &A[(size_t)(m0 + row) * lda + k0 + c4 * 4]);
            cp_async16(bbase + off, &B[(size_t)(n0 + row) * ldb + k0 + c4 * 4]);
        }
    };

    preload(0, 0);
    CP_COMMIT();

    for (int c = 0; c < nc; c++) {
        const int s = c & 1;
        if (c + 1 < nc) {
            preload(c + 1, s ^ 1);
            CP_COMMIT();
            CP_WAIT(1);
        } else {
            CP_WAIT(0);
        }
        __syncthreads();

        const float* As = smem + s * STAGE_FLOATS;
        const float* Bs = As + AB_FLOATS;

#pragma unroll
        for (int ks = 0; ks < 4; ks++) {
            uint32_t af[2][4];
#pragma unroll
            for (int mt = 0; mt < 2; mt++) {
                const int r  = wm * 32 + mt * 16 + lq;
                const int cI = ks * 8 + lr;
                float a0 = As[(r    ) * PADK + cI    ];
                float a1 = As[(r + 8) * PADK + cI    ];
                float a2 = As[(r    ) * PADK + cI + 4];
                float a3 = As[(r + 8) * PADK + cI + 4];
                if (CVTA) {
                    af[mt][0] = f2tf(a0); af[mt][1] = f2tf(a1);
                    af[mt][2] = f2tf(a2); af[mt][3] = f2tf(a3);
                } else {
                    af[mt][0] = __float_as_uint(a0); af[mt][1] = __float_as_uint(a1);
                    af[mt][2] = __float_as_uint(a2); af[mt][3] = __float_as_uint(a3);
                }
            }
#pragma unroll
            for (int nt = 0; nt < 8; nt++) {
                const int n  = wn * 64 + nt * 8 + lq;
                const int cI = ks * 8 + lr;
                uint32_t bf[2];
                bf[0] = __float_as_uint(Bs[n * PADK + cI    ]);
                bf[1] = __float_as_uint(Bs[n * PADK + cI + 4]);
                mma8(acc[0][nt], af[0], bf);
                mma8(acc[1][nt], af[1], bf);
            }
        }
        __syncthreads();
    }

    // ---- epilogue: regs -> staged smem (alpha/exp) -> coalesced GMEM ----
    float* stg = smem;                                // 128 x 132 floats
#pragma unroll
    for (int mt = 0; mt < 2; mt++) {
        const int r = wm * 32 + mt * 16 + lq;
#pragma unroll
        for (int nt = 0; nt < 8; nt++) {
            const int cI = wn * 64 + nt * 8 + 2 * lr;
            float v0 = acc[mt][nt][0] * alpha;
            float v1 = acc[mt][nt][1] * alpha;
            float v2 = acc[mt][nt][2] * alpha;
            float v3 = acc[mt][nt][3] * alpha;
            if (EPI == 2) {
                v0 = __expf(v0 - 6.0f); v1 = __expf(v1 - 6.0f);
                v2 = __expf(v2 - 6.0f); v3 = __expf(v3 - 6.0f);
            }
            *(float2*)&stg[(r    ) * 132 + cI] = make_float2(v0, v1);
            *(float2*)&stg[(r + 8) * 132 + cI] = make_float2(v2, v3);
        }
    }
    __syncthreads();

    if (EPI == 2) {
        const int row  = tid >> 1;
        const int half = tid & 1;
        float s = 0.0f;
#pragma unroll
        for (int j4 = 0; j4 < 16; j4++) {
            float4 v = *(const float4*)&stg[row * 132 + half * 64 + j4 * 4];
            s += v.x + v.y + v.z + v.w;
        }
        s += __shfl_xor_sync(0xFFFFFFFFu, s, 1);
        if (half == 0)
            partial[(size_t)(z * 16 + blockIdx.x) * Lc + m0 + row] = s;
    }

    float4 bv = make_float4(0.f, 0.f, 0.f, 0.f);
    if (EPI == 1) bv = *(const float4*)&bias[n0 + lane * 4];
#pragma unroll
    for (int it = 0; it < 16; it++) {
        const int r2 = it * 8 + wid;
        float4 v = *(const float4*)&stg[r2 * 132 + lane * 4];
        if (EPI == 1) {
            v.x = roundtf(v.x + bv.x); v.y = roundtf(v.y + bv.y);
            v.z = roundtf(v.z + bv.z); v.w = roundtf(v.w + bv.w);
        }
        if (EPI == 2) {
            __half2 h0 = __floats2half2_rn(v.x, v.y);
            __half2 h1 = __floats2half2_rn(v.z, v.w);
            uint2 u;
            u.x = *(uint32_t*)&h0; u.y = *(uint32_t*)&h1;
            *(uint2*)&C[(size_t)(m0 + r2) * ldc + n0 + lane * 4] = u;
        } else {
            *(float4*)&C[(size_t)(m0 + r2) * ldc + n0 + lane * 4] = v;
        }
    }
}

// ---------------------------------------------------------------------------
// elementwise tf32 rounding: dst = round_tf32(src)
// ---------------------------------------------------------------------------
__global__ __launch_bounds__(256)
void round_kernel(const float* __restrict__ src, float* __restrict__ dst)
{
    const int i = (blockIdx.x * 256 + threadIdx.x) * 4;
    float4 v = *(const float4*)&src[i];
    v.x = roundtf(v.x); v.y = roundtf(v.y);
    v.z = roundtf(v.z); v.w = roundtf(v.w);
    *(float4*)&dst[i] = v;
}

// x [B,L,D] -> xT [B,D,L], tf32-rounded
__global__ __launch_bounds__(256)
void transpose_kernel(const float* __restrict__ x, float* __restrict__ xT)
{
    __shared__ float t[32][33];
    const int b  = blockIdx.z;
    const int l0 = blockIdx.y * 32;
    const int d0 = blockIdx.x * 32;
    const int tx = threadIdx.x, ty = threadIdx.y;
#pragma unroll
    for (int j = 0; j < 4; j++)
        t[ty + 8 * j][tx] = x[(size_t)b * Lc * Dc + (size_t)(l0 + ty + 8 * j) * Dc + d0 + tx];
    __syncthreads();
#pragma unroll
    for (int j = 0; j < 4; j++)
        xT[(size_t)b * Dc * Lc + (size_t)(d0 + ty + 8 * j) * Lc + l0 + tx] =
            roundtf(t[tx][ty + 8 * j]);
}

// gs[z][q] = sum over 16 n-tiles of partial sums
__global__ __launch_bounds__(256)
void reduce_gs_kernel(const float* __restrict__ partial, float* __restrict__ gs)
{
    const int i = blockIdx.x * 256 + threadIdx.x;
    const int z = i >> 11, q = i & (Lc - 1);
    float s = 0.0f;
#pragma unroll
    for (int kt = 0; kt < 16; kt++)
        s += partial[(size_t)(z * 16 + kt) * Lc + q];
    gs[i] = s;
}

// ---------------------------------------------------------------------------
// Per (b,q): head-mean of exp-scores (fp16), temporal decay, renormalize.
// Each thread owns 8 consecutive cols (one 16B half-vector per head).
// ---------------------------------------------------------------------------
__global__ __launch_bounds__(256)
void attn_kernel(const __half* __restrict__ E, const float* __restrict__ gs,
                 const float* __restrict__ td, float* __restrict__ attn)
{
    const int bq = blockIdx.x;            // 0..4095
    const int b  = bq >> 11;
    const int q  = bq & (Lc - 1);
    const int tid = threadIdx.x;

    __shared__ float ish[Hc];
    __shared__ float red[8];

    if (tid < Hc)
        ish[tid] = 1.0f / (16.0f * gs[(b * Hc + tid) * Lc + q]);
    __syncthreads();

    float acc[8];
#pragma unroll
    for (int j = 0; j < 8; j++) acc[j] = 0.0f;

#pragma unroll
    for (int h = 0; h < Hc; h++) {
        const uint4 u = *(const uint4*)&E[((size_t)(b * Hc + h) * Lc + q) * Lc + 8 * tid];
        const float is = ish[h];
        float2 f0 = __half22float2(*(const __half2*)&u.x);
        float2 f1 = __half22float2(*(const __half2*)&u.y);
        float2 f2 = __half22float2(*(const __half2*)&u.z);
        float2 f3 = __half22float2(*(const __half2*)&u.w);
        acc[0] += f0.x * is; acc[1] += f0.y * is;
        acc[2] += f1.x * is; acc[3] += f1.y * is;
        acc[4] += f2.x * is; acc[5] += f2.y * is;
        acc[6] += f3.x * is; acc[7] += f3.y * is;
    }

    const float4 t0 = *(const float4*)&td[(size_t)bq * Lc + 8 * tid];
    const float4 t1 = *(const float4*)&td[(size_t)bq * Lc + 8 * tid + 4];
    float w[8];
    w[0] = acc[0] * __expf(-0.1f * t0.x);
    w[1] = acc[1] * __expf(-0.1f * t0.y);
    w[2] = acc[2] * __expf(-0.1f * t0.z);
    w[3] = acc[3] * __expf(-0.1f * t0.w);
    w[4] = acc[4] * __expf(-0.1f * t1.x);
    w[5] = acc[5] * __expf(-0.1f * t1.y);
    w[6] = acc[6] * __expf(-0.1f * t1.z);
    w[7] = acc[7] * __expf(-0.1f * t1.w);

    float lsum = 0.0f;
#pragma unroll
    for (int j = 0; j < 8; j++) lsum += w[j];
#pragma unroll
    for (int o = 16; o; o >>= 1) lsum += __shfl_xor_sync(0xFFFFFFFFu, lsum, o);
    if ((tid & 31) == 0) red[tid >> 5] = lsum;
    __syncthreads();
    if (tid == 0) {
        float t = 0.0f;
#pragma unroll
        for (int i = 0; i < 8; i++) t += red[i];
        red[0] = 1.0f / (t + 1e-8f);
    }
    __syncthreads();
    const float inv = red[0];

    float4 o0, o1;
    o0.x = w[0] * inv; o0.y = w[1] * inv; o0.z = w[2] * inv; o0.w = w[3] * inv;
    o1.x = w[4] * inv; o1.y = w[5] * inv; o1.z = w[6] * inv; o1.w = w[7] * inv;
    *(float4*)&attn[(size_t)bq * Lc + 8 * tid]     = o0;
    *(float4*)&attn[(size_t)bq * Lc + 8 * tid + 4] = o1;
}

// ---------------------------------------------------------------------------
extern "C" void kernel_launch(void* const* d_in, const int* in_sizes, int n_in,
                              void* d_out, int out_size)
{
    const float* x    = (const float*)d_in[0];   // [B,L,D]
    const float* td   = (const float*)d_in[1];   // [B,L,L]
    const float* W    = (const float*)d_in[2];   // [3D,D]
    const float* bias = (const float*)d_in[3];   // [3D]
    float* out = (float*)d_out;

    float *qk, *xT, *xR, *WR, *part, *gs, *attn_scratch;
    __half* S;
    cudaGetSymbolAddress((void**)&qk, g_qk);
    cudaGetSymbolAddress((void**)&S, g_S);
    cudaGetSymbolAddress((void**)&xT, g_xT);
    cudaGetSymbolAddress((void**)&xR, g_xR);
    cudaGetSymbolAddress((void**)&WR, g_WR);
    cudaGetSymbolAddress((void**)&part, g_part);
    cudaGetSymbolAddress((void**)&gs, g_gs);
    cudaGetSymbolAddress((void**)&attn_scratch, g_attn);

    cudaFuncSetAttribute(gemm_tc<0, true,  float>,  cudaFuncAttributeMaxDynamicSharedMemorySize, SMEM_GEMM_BYTES);
    cudaFuncSetAttribute(gemm_tc<1, false, float>,  cudaFuncAttributeMaxDynamicSharedMemorySize, SMEM_GEMM_BYTES);
    cudaFuncSetAttribute(gemm_tc<2, false, __half>, cudaFuncAttributeMaxDynamicSharedMemorySize, SMEM_GEMM_BYTES);

    const long outElems  = (long)Bc * Lc * Dc;   // 4,194,304
    const long attnElems = (long)Bc * Lc * Lc;   // 8,388,608
    float* out_o = out;
    float* out_a = ((long)out_size >= outElems + attnElems) ? (out + outElems)
                                                            : attn_scratch;

    // Prep: tf32-round x and W[:2048]; build rounded x^T
    round_kernel<<<(Bc * Lc * Dc) / 1024, 256>>>(x, xR);
    round_kernel<<<(2 * Dc * Dc) / 1024, 256>>>(W, WR);
    {
        dim3 grid(Dc / 32, Lc / 32, Bc);
        transpose_kernel<<<grid, dim3(32, 8)>>>(x, xT);
    }

    // K1: qk = tf32round(xR @ WR^T + bias)
    {
        dim3 grid(2 * Dc / 128, (Bc * Lc) / 128, 1);
        gemm_tc<1, false, float><<<grid, 256, SMEM_GEMM_BYTES>>>(
            xR, Dc, 0, 0,
            WR, Dc, 0, 0,
            qk, 2 * Dc, 0, 0,
            1, Dc, 1.0f, bias, nullptr);
    }

    // K2: S[b,h] = fp16(exp(0.125*Q@K^T - 6)), fused per-row partial sums
    {
        dim3 grid(Lc / 128, Lc / 128, Bc * Hc);
        gemm_tc<2, false, __half><<<grid, 256, SMEM_GEMM_BYTES>>>(
            qk,       2 * Dc, (long)Lc * 2 * Dc, 64,
            qk + Dc,  2 * Dc, (long)Lc * 2 * Dc, 64,
            S,        Lc,     (long)Hc * Lc * Lc, (long)Lc * Lc,
            Hc, 64, 0.125f, nullptr, part);
    }

    // K3: gs = sum of partials
    reduce_gs_kernel<<<(Bc * Hc * Lc) / 256, 256>>>(part, gs);

    // K4: head-mean + decay + renormalize -> attn (fp32)
    attn_kernel<<<Bc * Lc, 256>>>(S, gs, td, out_a);

    // K5: output = attn @ x  (A cvt in-register; B = pre-rounded xT)
    {
        dim3 grid(Dc / 128, Lc / 128, Bc);
        gemm_tc<0, true, float><<<grid, 256, SMEM_GEMM_BYTES>>>(
            out_a, Lc, (long)Lc * Lc, 0,
            xT,    Lc, (long)Dc * Lc, 0,
            out_o, Dc, (long)Lc * Dc, 0,
            1, Lc, 1.0f, nullptr, nullptr);
    }
}

// round 5
// speedup vs baseline: 4.4503x; 1.4736x over previous
#include <cuda_runtime.h>
#include <cuda_fp16.h>
#include <cstdint>

// Problem constants
static constexpr int Bc  = 2;
static constexpr int Lc  = 2048;
static constexpr int Dc  = 1024;
static constexpr int Hc  = 16;

// Scratch (__device__ globals: allocation-free rule)
__device__ __half g_qk  [(size_t)Bc * Lc * 2 * Dc];     // [4096][2048] q|k fp16
__device__ __half g_S   [(size_t)Bc * Hc * Lc * Lc];    // exp(score-6) fp16 (268 MB)
__device__ __half g_xh  [(size_t)Bc * Lc * Dc];         // x fp16
__device__ __half g_Wh  [(size_t)2 * Dc * Dc];          // W[:2048] fp16
__device__ __half g_xTh [(size_t)Bc * Dc * Lc];         // x^T fp16
__device__ __half g_atnH[(size_t)Bc * Lc * Lc];         // attn fp16 (K5 operand)
__device__ float  g_part[(size_t)Bc * Hc * 16 * Lc];    // per-ntile row sums
__device__ float  g_gs  [Bc * Hc * Lc];                 // per (b,h,q) sumexp
__device__ float  g_attn[(size_t)Bc * Lc * Lc];         // fallback attn buffer

// ---------------------------------------------------------------------------
__device__ __forceinline__ uint32_t smem_u32(const void* p) {
    uint32_t a;
    asm("{ .reg .u64 t; cvta.to.shared.u64 t, %1; cvt.u32.u64 %0, t; }" : "=r"(a) : "l"(p));
    return a;
}
__device__ __forceinline__ void mma16(float* c, const uint32_t* a, const uint32_t* b) {
    asm volatile(
        "mma.sync.aligned.m16n8k16.row.col.f32.f16.f16.f32 "
        "{%0,%1,%2,%3}, {%4,%5,%6,%7}, {%8,%9}, {%0,%1,%2,%3};"
        : "+f"(c[0]), "+f"(c[1]), "+f"(c[2]), "+f"(c[3])
        : "r"(a[0]), "r"(a[1]), "r"(a[2]), "r"(a[3]), "r"(b[0]), "r"(b[1]));
}
#define LDMX4(r0, r1, r2, r3, addr) \
    asm volatile("ldmatrix.sync.aligned.m8n8.x4.shared.b16 {%0,%1,%2,%3}, [%4];" \
        : "=r"(r0), "=r"(r1), "=r"(r2), "=r"(r3) : "r"(addr))
__device__ __forceinline__ void cp_async16(uint32_t dst, const void* src) {
    asm volatile("cp.async.cg.shared.global [%0], [%1], 16;" :: "r"(dst), "l"(src));
}
#define CP_COMMIT() asm volatile("cp.async.commit_group;" ::: "memory")
#define CP_WAIT(N)  asm volatile("cp.async.wait_group %0;" :: "n"(N) : "memory")

// ---------------------------------------------------------------------------
// fp16 warp-MMA GEMM: C[128x128/blk] = f(alpha * A @ B^T)  (A,B K-major fp16)
// EPI: 0 = fp32 store, 1 = +bias -> fp16, 2 = exp(v-6) -> fp16 + row sums
// 256 thr = 8 warps (4m x 2n), warp tile 32x64, mma m16n8k16, ldmatrix.x4.
// 4-stage cp.async pipeline; epilogue stages fp32 in smem for coalescing.
// ---------------------------------------------------------------------------
static constexpr int PADH = 40;                         // 32 + 8 pad halves
static constexpr int AB_HALVES = 128 * PADH;            // 5120
static constexpr int STAGE_HALVES = 2 * AB_HALVES;      // A then B
static constexpr int NSTAGE = 4;
static constexpr int SMEM_GEMM_BYTES = NSTAGE * STAGE_HALVES * 2;   // 81920

template <int EPI, typename CT>
__global__ __launch_bounds__(256, 2)
void gemm_h(const __half* __restrict__ A, int lda, long aOut, long aIn,
            const __half* __restrict__ B, int ldb, long bOut, long bIn,
            CT* __restrict__ C, int ldc, long cOut, long cIn,
            int zInner, int Kd, float alpha,
            const float* __restrict__ bias, float* __restrict__ partial)
{
    extern __shared__ __align__(16) char smemc[];
    const uint32_t sb = smem_u32(smemc);

    const int tid  = threadIdx.x;
    const int wid  = tid >> 5;
    const int lane = tid & 31;
    const int wm   = wid >> 1;          // 0..3
    const int wn   = wid & 1;           // 0..1
    const int lq   = lane >> 2;         // 0..7
    const int lr   = lane & 3;          // 0..3

    const int z  = blockIdx.z;
    const int zo = z / zInner, zi = z % zInner;
    A += (long)zo * aOut + (long)zi * aIn;
    B += (long)zo * bOut + (long)zi * bIn;
    C += (long)zo * cOut + (long)zi * cIn;

    const int m0 = blockIdx.y * 128;
    const int n0 = blockIdx.x * 128;

    float acc[2][8][4];
#pragma unroll
    for (int mt = 0; mt < 2; mt++)
#pragma unroll
        for (int nt = 0; nt < 8; nt++)
#pragma unroll
            for (int i = 0; i < 4; i++) acc[mt][nt][i] = 0.0f;

    const int nc = Kd / 32;

    auto preload = [&](int c) {
        const int s  = c & 3;
        const int k0 = c * 32;
        const uint32_t abase = sb + (uint32_t)(s * STAGE_HALVES) * 2;
        const uint32_t bbase = abase + (uint32_t)AB_HALVES * 2;
#pragma unroll
        for (int j = 0; j < 2; j++) {
            const int f   = j * 256 + tid;
            const int row = f >> 2;
            const int c8  = f & 3;
            const uint32_t off = (uint32_t)(row * PADH + c8 * 8) * 2;
            cp_async16(abase + off, &A[(size_t)(m0 + row) * lda + k0 + c8 * 8]);
            cp_async16(bbase + off, &B[(size_t)(n0 + row) * ldb + k0 + c8 * 8]);
        }
    };

#pragma unroll
    for (int p = 0; p < 3; p++) {
        if (p < nc) { preload(p); CP_COMMIT(); }
    }

    for (int c = 0; c < nc; c++) {
        const int rem = nc - 1 - c;
        if (rem >= 2) { CP_WAIT(2); }
        else if (rem == 1) { CP_WAIT(1); }
        else { CP_WAIT(0); }
        __syncthreads();

        const uint32_t stA = sb + (uint32_t)((c & 3) * STAGE_HALVES) * 2;
        const uint32_t stB = stA + (uint32_t)AB_HALVES * 2;

#pragma unroll
        for (int kh = 0; kh < 2; kh++) {
            uint32_t af[2][4];
#pragma unroll
            for (int mt = 0; mt < 2; mt++) {
                const int row = wm * 32 + mt * 16 + (lane & 7) + ((lane >> 3) & 1) * 8;
                const int col = kh * 16 + (lane >> 4) * 8;
                LDMX4(af[mt][0], af[mt][1], af[mt][2], af[mt][3],
                      stA + (uint32_t)(row * PADH + col) * 2);
            }
#pragma unroll
            for (int np = 0; np < 4; np++) {
                const int rowb = wn * 64 + np * 16 + (lane >> 4) * 8 + (lane & 7);
                const int colk = kh * 16 + ((lane >> 3) & 1) * 8;
                uint32_t bf[4];
                LDMX4(bf[0], bf[1], bf[2], bf[3],
                      stB + (uint32_t)(rowb * PADH + colk) * 2);
                mma16(acc[0][np * 2    ], af[0], bf + 0);
                mma16(acc[1][np * 2    ], af[1], bf + 0);
                mma16(acc[0][np * 2 + 1], af[0], bf + 2);
                mma16(acc[1][np * 2 + 1], af[1], bf + 2);
            }
        }
        __syncthreads();
        if (c + 3 < nc) { preload(c + 3); CP_COMMIT(); }
    }

    // ---- epilogue: regs -> fp32 staged smem -> coalesced GMEM ----
    float* stg = (float*)smemc;                        // 128 x 132 floats (67.6KB)
#pragma unroll
    for (int mt = 0; mt < 2; mt++) {
        const int r = wm * 32 + mt * 16 + lq;
#pragma unroll
        for (int nt = 0; nt < 8; nt++) {
            const int cI = wn * 64 + nt * 8 + 2 * lr;
            float v0 = acc[mt][nt][0] * alpha;
            float v1 = acc[mt][nt][1] * alpha;
            float v2 = acc[mt][nt][2] * alpha;
            float v3 = acc[mt][nt][3] * alpha;
            if (EPI == 2) {
                v0 = __expf(v0 - 6.0f); v1 = __expf(v1 - 6.0f);
                v2 = __expf(v2 - 6.0f); v3 = __expf(v3 - 6.0f);
            }
            *(float2*)&stg[(r    ) * 132 + cI] = make_float2(v0, v1);
            *(float2*)&stg[(r + 8) * 132 + cI] = make_float2(v2, v3);
        }
    }
    __syncthreads();

    if (EPI == 2) {
        const int row  = tid >> 1;
        const int half = tid & 1;
        float s = 0.0f;
#pragma unroll
        for (int j4 = 0; j4 < 16; j4++) {
            float4 v = *(const float4*)&stg[row * 132 + half * 64 + j4 * 4];
            s += v.x + v.y + v.z + v.w;
        }
        s += __shfl_xor_sync(0xFFFFFFFFu, s, 1);
        if (half == 0)
            partial[(size_t)(z * 16 + blockIdx.x) * Lc + m0 + row] = s;
    }

    float4 bv = make_float4(0.f, 0.f, 0.f, 0.f);
    if (EPI == 1) bv = *(const float4*)&bias[n0 + lane * 4];
#pragma unroll
    for (int it = 0; it < 16; it++) {
        const int r2 = it * 8 + wid;
        float4 v = *(const float4*)&stg[r2 * 132 + lane * 4];
        if (EPI == 1) { v.x += bv.x; v.y += bv.y; v.z += bv.z; v.w += bv.w; }
        if (EPI == 0) {
            *(float4*)&C[(size_t)(m0 + r2) * ldc + n0 + lane * 4] = v;
        } else {
            __half2 h0 = __floats2half2_rn(v.x, v.y);
            __half2 h1 = __floats2half2_rn(v.z, v.w);
            uint2 u;
            u.x = *(uint32_t*)&h0; u.y = *(uint32_t*)&h1;
            *(uint2*)&C[(size_t)(m0 + r2) * ldc + n0 + lane * 4] = u;
        }
    }
}

// ---------------------------------------------------------------------------
// fp32 -> fp16 elementwise (8 per thread)
// ---------------------------------------------------------------------------
__global__ __launch_bounds__(256)
void conv_h_kernel(const float* __restrict__ src, __half* __restrict__ dst)
{
    const size_t i = ((size_t)blockIdx.x * 256 + threadIdx.x) * 8;
    float4 a = *(const float4*)&src[i];
    float4 b = *(const float4*)&src[i + 4];
    __half2 h0 = __floats2half2_rn(a.x, a.y);
    __half2 h1 = __floats2half2_rn(a.z, a.w);
    __half2 h2 = __floats2half2_rn(b.x, b.y);
    __half2 h3 = __floats2half2_rn(b.z, b.w);
    uint4 u;
    u.x = *(uint32_t*)&h0; u.y = *(uint32_t*)&h1;
    u.z = *(uint32_t*)&h2; u.w = *(uint32_t*)&h3;
    *(uint4*)&dst[i] = u;
}

// x [B,L,D] -> xT [B,D,L] fp16
__global__ __launch_bounds__(256)
void transpose_h_kernel(const float* __restrict__ x, __half* __restrict__ xT)
{
    __shared__ float t[32][33];
    const int b  = blockIdx.z;
    const int l0 = blockIdx.y * 32;
    const int d0 = blockIdx.x * 32;
    const int tx = threadIdx.x, ty = threadIdx.y;
#pragma unroll
    for (int j = 0; j < 4; j++)
        t[ty + 8 * j][tx] = x[(size_t)b * Lc * Dc + (size_t)(l0 + ty + 8 * j) * Dc + d0 + tx];
    __syncthreads();
#pragma unroll
    for (int j = 0; j < 4; j++)
        xT[(size_t)b * Dc * Lc + (size_t)(d0 + ty + 8 * j) * Lc + l0 + tx] =
            __float2half_rn(t[tx][ty + 8 * j]);
}

// gs[z][q] = sum over 16 n-tiles of partial sums
__global__ __launch_bounds__(256)
void reduce_gs_kernel(const float* __restrict__ partial, float* __restrict__ gs)
{
    const int i = blockIdx.x * 256 + threadIdx.x;
    const int z = i >> 11, q = i & (Lc - 1);
    float s = 0.0f;
#pragma unroll
    for (int kt = 0; kt < 16; kt++)
        s += partial[(size_t)(z * 16 + kt) * Lc + q];
    gs[i] = s;
}

// ---------------------------------------------------------------------------
// Per (b,q): head-mean of exp-scores (fp16), decay, renormalize.
// Writes fp32 attn (output) and fp16 attn (K5 operand).
// ---------------------------------------------------------------------------
__global__ __launch_bounds__(256)
void attn_kernel(const __half* __restrict__ E, const float* __restrict__ gs,
                 const float* __restrict__ td, float* __restrict__ attn,
                 __half* __restrict__ attnH)
{
    const int bq = blockIdx.x;            // 0..4095
    const int b  = bq >> 11;
    const int q  = bq & (Lc - 1);
    const int tid = threadIdx.x;

    __shared__ float ish[Hc];
    __shared__ float red[8];

    if (tid < Hc)
        ish[tid] = 1.0f / (16.0f * gs[(b * Hc + tid) * Lc + q]);
    __syncthreads();

    float acc[8];
#pragma unroll
    for (int j = 0; j < 8; j++) acc[j] = 0.0f;

#pragma unroll
    for (int h = 0; h < Hc; h++) {
        const uint4 u = *(const uint4*)&E[((size_t)(b * Hc + h) * Lc + q) * Lc + 8 * tid];
        const float is = ish[h];
        float2 f0 = __half22float2(*(const __half2*)&u.x);
        float2 f1 = __half22float2(*(const __half2*)&u.y);
        float2 f2 = __half22float2(*(const __half2*)&u.z);
        float2 f3 = __half22float2(*(const __half2*)&u.w);
        acc[0] += f0.x * is; acc[1] += f0.y * is;
        acc[2] += f1.x * is; acc[3] += f1.y * is;
        acc[4] += f2.x * is; acc[5] += f2.y * is;
        acc[6] += f3.x * is; acc[7] += f3.y * is;
    }

    const float4 t0 = *(const float4*)&td[(size_t)bq * Lc + 8 * tid];
    const float4 t1 = *(const float4*)&td[(size_t)bq * Lc + 8 * tid + 4];
    float w[8];
    w[0] = acc[0] * __expf(-0.1f * t0.x);
    w[1] = acc[1] * __expf(-0.1f * t0.y);
    w[2] = acc[2] * __expf(-0.1f * t0.z);
    w[3] = acc[3] * __expf(-0.1f * t0.w);
    w[4] = acc[4] * __expf(-0.1f * t1.x);
    w[5] = acc[5] * __expf(-0.1f * t1.y);
    w[6] = acc[6] * __expf(-0.1f * t1.z);
    w[7] = acc[7] * __expf(-0.1f * t1.w);

    float lsum = 0.0f;
#pragma unroll
    for (int j = 0; j < 8; j++) lsum += w[j];
#pragma unroll
    for (int o = 16; o; o >>= 1) lsum += __shfl_xor_sync(0xFFFFFFFFu, lsum, o);
    if ((tid & 31) == 0) red[tid >> 5] = lsum;
    __syncthreads();
    if (tid == 0) {
        float t = 0.0f;
#pragma unroll
        for (int i = 0; i < 8; i++) t += red[i];
        red[0] = 1.0f / (t + 1e-8f);
    }
    __syncthreads();
    const float inv = red[0];

    float o[8];
#pragma unroll
    for (int j = 0; j < 8; j++) o[j] = w[j] * inv;
    *(float4*)&attn[(size_t)bq * Lc + 8 * tid]     = make_float4(o[0], o[1], o[2], o[3]);
    *(float4*)&attn[(size_t)bq * Lc + 8 * tid + 4] = make_float4(o[4], o[5], o[6], o[7]);

    __half2 h0 = __floats2half2_rn(o[0], o[1]);
    __half2 h1 = __floats2half2_rn(o[2], o[3]);
    __half2 h2 = __floats2half2_rn(o[4], o[5]);
    __half2 h3 = __floats2half2_rn(o[6], o[7]);
    uint4 u;
    u.x = *(uint32_t*)&h0; u.y = *(uint32_t*)&h1;
    u.z = *(uint32_t*)&h2; u.w = *(uint32_t*)&h3;
    *(uint4*)&attnH[(size_t)bq * Lc + 8 * tid] = u;
}

// ---------------------------------------------------------------------------
extern "C" void kernel_launch(void* const* d_in, const int* in_sizes, int n_in,
                              void* d_out, int out_size)
{
    const float* x    = (const float*)d_in[0];   // [B,L,D]
    const float* td   = (const float*)d_in[1];   // [B,L,L]
    const float* W    = (const float*)d_in[2];   // [3D,D]
    const float* bias = (const float*)d_in[3];   // [3D]
    float* out = (float*)d_out;

    __half *qk, *S, *xh, *Wh, *xTh, *atnH;
    float *part, *gs, *attn_scratch;
    cudaGetSymbolAddress((void**)&qk, g_qk);
    cudaGetSymbolAddress((void**)&S, g_S);
    cudaGetSymbolAddress((void**)&xh, g_xh);
    cudaGetSymbolAddress((void**)&Wh, g_Wh);
    cudaGetSymbolAddress((void**)&xTh, g_xTh);
    cudaGetSymbolAddress((void**)&atnH, g_atnH);
    cudaGetSymbolAddress((void**)&part, g_part);
    cudaGetSymbolAddress((void**)&gs, g_gs);
    cudaGetSymbolAddress((void**)&attn_scratch, g_attn);

    cudaFuncSetAttribute(gemm_h<0, float>,  cudaFuncAttributeMaxDynamicSharedMemorySize, SMEM_GEMM_BYTES);
    cudaFuncSetAttribute(gemm_h<1, __half>, cudaFuncAttributeMaxDynamicSharedMemorySize, SMEM_GEMM_BYTES);
    cudaFuncSetAttribute(gemm_h<2, __half>, cudaFuncAttributeMaxDynamicSharedMemorySize, SMEM_GEMM_BYTES);

    const long outElems  = (long)Bc * Lc * Dc;   // 4,194,304
    const long attnElems = (long)Bc * Lc * Lc;   // 8,388,608
    float* out_o = out;
    float* out_a = ((long)out_size >= outElems + attnElems) ? (out + outElems)
                                                            : attn_scratch;

    // Prep: fp16 copies of x, W[:2048]; fp16 x^T
    conv_h_kernel<<<(Bc * Lc * Dc) / 2048, 256>>>(x, xh);
    conv_h_kernel<<<(2 * Dc * Dc) / 2048, 256>>>(W, Wh);
    {
        dim3 grid(Dc / 32, Lc / 32, Bc);
        transpose_h_kernel<<<grid, dim3(32, 8)>>>(x, xTh);
    }

    // K1: qk = fp16(xh @ Wh^T + bias)
    {
        dim3 grid(2 * Dc / 128, (Bc * Lc) / 128, 1);
        gemm_h<1, __half><<<grid, 256, SMEM_GEMM_BYTES>>>(
            xh, Dc, 0, 0,
            Wh, Dc, 0, 0,
            qk, 2 * Dc, 0, 0,
            1, Dc, 1.0f, bias, nullptr);
    }

    // K2: S[b,h] = fp16(exp(0.125*Q@K^T - 6)), fused per-row partial sums
    {
        dim3 grid(Lc / 128, Lc / 128, Bc * Hc);
        gemm_h<2, __half><<<grid, 256, SMEM_GEMM_BYTES>>>(
            qk,       2 * Dc, (long)Lc * 2 * Dc, 64,
            qk + Dc,  2 * Dc, (long)Lc * 2 * Dc, 64,
            S,        Lc,     (long)Hc * Lc * Lc, (long)Lc * Lc,
            Hc, 64, 0.125f, nullptr, part);
    }

    // K3: gs = sum of partials
    reduce_gs_kernel<<<(Bc * Hc * Lc) / 256, 256>>>(part, gs);

    // K4: head-mean + decay + renormalize -> attn fp32 + fp16
    attn_kernel<<<Bc * Lc, 256>>>(S, gs, td, out_a, atnH);

    // K5: output = attnH @ xTh^T  (both fp16, K=2048)
    {
        dim3 grid(Dc / 128, Lc / 128, Bc);
        gemm_h<0, float><<<grid, 256, SMEM_GEMM_BYTES>>>(
            atnH, Lc, (long)Lc * Lc, 0,
            xTh,  Lc, (long)Dc * Lc, 0,
            out_o, Dc, (long)Lc * Dc, 0,
            1, Lc, 1.0f, nullptr, nullptr);
    }
}

// round 6
// speedup vs baseline: 4.6110x; 1.0361x over previous
#include <cuda_runtime.h>
#include <cuda_fp16.h>
#include <cstdint>

// Problem constants
static constexpr int Bc  = 2;
static constexpr int Lc  = 2048;
static constexpr int Dc  = 1024;
static constexpr int Hc  = 16;

// Scratch (__device__ globals: allocation-free rule)
__device__ __half g_qk  [(size_t)Bc * Lc * 2 * Dc];     // [4096][2048] q|k fp16
__device__ __half g_S   [(size_t)Bc * Hc * Lc * Lc];    // exp(score-6) fp16 (268 MB)
__device__ __half g_xh  [(size_t)Bc * Lc * Dc];         // x fp16
__device__ __half g_Wh  [(size_t)2 * Dc * Dc];          // W[:2048] fp16
__device__ __half g_xTh [(size_t)Bc * Dc * Lc];         // x^T fp16
__device__ __half g_atnH[(size_t)Bc * Lc * Lc];         // attn fp16 (K5 operand)
__device__ float  g_part[(size_t)Bc * Hc * 16 * Lc];    // per-ntile row sums
__device__ float  g_gs  [Bc * Hc * Lc];                 // per (b,h,q) sumexp
__device__ float  g_attn[(size_t)Bc * Lc * Lc];         // fallback attn buffer

// ---------------------------------------------------------------------------
__device__ __forceinline__ uint32_t smem_u32(const void* p) {
    uint32_t a;
    asm("{ .reg .u64 t; cvta.to.shared.u64 t, %1; cvt.u32.u64 %0, t; }" : "=r"(a) : "l"(p));
    return a;
}
__device__ __forceinline__ void mma16(float* c, const uint32_t* a, const uint32_t* b) {
    asm volatile(
        "mma.sync.aligned.m16n8k16.row.col.f32.f16.f16.f32 "
        "{%0,%1,%2,%3}, {%4,%5,%6,%7}, {%8,%9}, {%0,%1,%2,%3};"
        : "+f"(c[0]), "+f"(c[1]), "+f"(c[2]), "+f"(c[3])
        : "r"(a[0]), "r"(a[1]), "r"(a[2]), "r"(a[3]), "r"(b[0]), "r"(b[1]));
}
#define LDMX4(r0, r1, r2, r3, addr) \
    asm volatile("ldmatrix.sync.aligned.m8n8.x4.shared.b16 {%0,%1,%2,%3}, [%4];" \
        : "=r"(r0), "=r"(r1), "=r"(r2), "=r"(r3) : "r"(addr))
__device__ __forceinline__ void cp_async16(uint32_t dst, const void* src) {
    asm volatile("cp.async.cg.shared.global [%0], [%1], 16;" :: "r"(dst), "l"(src));
}
#define CP_COMMIT() asm volatile("cp.async.commit_group;" ::: "memory")
#define CP_WAIT(N)  asm volatile("cp.async.wait_group %0;" :: "n"(N) : "memory")

// ---------------------------------------------------------------------------
// fp16 warp-MMA GEMM: C[128x128/blk] = f(alpha * A @ B^T)  (A,B K-major fp16)
// EPI: 0 = fp32 store, 1 = +bias -> fp16, 2 = exp(v-6) -> fp16 + row sums
// 256 thr = 8 warps (4m x 2n), warp tile 32x64, mma m16n8k16, ldmatrix.x4.
// k-chunk 64, 3-stage cp.async ring, ONE barrier per chunk.
// ---------------------------------------------------------------------------
static constexpr int CHUNK = 64;
static constexpr int PADH  = 72;                        // 64 + 8 pad halves
static constexpr int AB_HALVES = 128 * PADH;            // 9216
static constexpr int STAGE_HALVES = 2 * AB_HALVES;      // A then B
static constexpr int NSTAGE = 3;
static constexpr int SMEM_GEMM_BYTES = NSTAGE * STAGE_HALVES * 2;   // 110592

template <int EPI, typename CT>
__global__ __launch_bounds__(256, 2)
void gemm_h(const __half* __restrict__ A, int lda, long aOut, long aIn,
            const __half* __restrict__ B, int ldb, long bOut, long bIn,
            CT* __restrict__ C, int ldc, long cOut, long cIn,
            int zInner, int Kd, float alpha,
            const float* __restrict__ bias, float* __restrict__ partial)
{
    extern __shared__ __align__(16) char smemc[];
    const uint32_t sb = smem_u32(smemc);

    const int tid  = threadIdx.x;
    const int wid  = tid >> 5;
    const int lane = tid & 31;
    const int wm   = wid >> 1;          // 0..3
    const int wn   = wid & 1;           // 0..1
    const int lq   = lane >> 2;         // 0..7
    const int lr   = lane & 3;          // 0..3

    const int z  = blockIdx.z;
    const int zo = z / zInner, zi = z % zInner;
    A += (long)zo * aOut + (long)zi * aIn;
    B += (long)zo * bOut + (long)zi * bIn;
    C += (long)zo * cOut + (long)zi * cIn;

    const int m0 = blockIdx.y * 128;
    const int n0 = blockIdx.x * 128;

    float acc[2][8][4];
#pragma unroll
    for (int mt = 0; mt < 2; mt++)
#pragma unroll
        for (int nt = 0; nt < 8; nt++)
#pragma unroll
            for (int i = 0; i < 4; i++) acc[mt][nt][i] = 0.0f;

    const int nc = Kd / CHUNK;

    // async copy one 128x64 A+B chunk into stage s
    auto preload = [&](int c, int s) {
        const int k0 = c * CHUNK;
        const uint32_t abase = sb + (uint32_t)(s * STAGE_HALVES) * 2;
        const uint32_t bbase = abase + (uint32_t)AB_HALVES * 2;
#pragma unroll
        for (int j = 0; j < 4; j++) {
            const int f   = j * 256 + tid;
            const int row = f >> 3;
            const int c8  = f & 7;
            const uint32_t off = (uint32_t)(row * PADH + c8 * 8) * 2;
            cp_async16(abase + off, &A[(size_t)(m0 + row) * lda + k0 + c8 * 8]);
            cp_async16(bbase + off, &B[(size_t)(n0 + row) * ldb + k0 + c8 * 8]);
        }
    };

    preload(0, 0);
    CP_COMMIT();
    if (nc > 1) { preload(1, 1); CP_COMMIT(); }

    int s = 0;
    for (int c = 0; c < nc; c++) {
        if (c + 1 < nc) { CP_WAIT(1); } else { CP_WAIT(0); }
        __syncthreads();
        // prefetch chunk c+2 into the stage freed by chunk c-1
        if (c + 2 < nc) {
            int s2 = s + 2; if (s2 >= NSTAGE) s2 -= NSTAGE;
            preload(c + 2, s2);
            CP_COMMIT();
        }

        const uint32_t stA = sb + (uint32_t)(s * STAGE_HALVES) * 2;
        const uint32_t stB = stA + (uint32_t)AB_HALVES * 2;

#pragma unroll
        for (int kh = 0; kh < CHUNK / 16; kh++) {
            uint32_t af[2][4];
#pragma unroll
            for (int mt = 0; mt < 2; mt++) {
                const int row = wm * 32 + mt * 16 + (lane & 7) + ((lane >> 3) & 1) * 8;
                const int col = kh * 16 + (lane >> 4) * 8;
                LDMX4(af[mt][0], af[mt][1], af[mt][2], af[mt][3],
                      stA + (uint32_t)(row * PADH + col) * 2);
            }
#pragma unroll
            for (int np = 0; np < 4; np++) {
                const int rowb = wn * 64 + np * 16 + (lane >> 4) * 8 + (lane & 7);
                const int colk = kh * 16 + ((lane >> 3) & 1) * 8;
                uint32_t bf[4];
                LDMX4(bf[0], bf[1], bf[2], bf[3],
                      stB + (uint32_t)(rowb * PADH + colk) * 2);
                mma16(acc[0][np * 2    ], af[0], bf + 0);
                mma16(acc[1][np * 2    ], af[1], bf + 0);
                mma16(acc[0][np * 2 + 1], af[0], bf + 2);
                mma16(acc[1][np * 2 + 1], af[1], bf + 2);
            }
        }
        if (++s >= NSTAGE) s -= NSTAGE;
    }
    __syncthreads();            // smem about to be reused by epilogue staging

    // ---- epilogue: regs -> fp32 staged smem -> coalesced GMEM ----
    float* stg = (float*)smemc;                        // 128 x 132 floats (67.6KB)
#pragma unroll
    for (int mt = 0; mt < 2; mt++) {
        const int r = wm * 32 + mt * 16 + lq;
#pragma unroll
        for (int nt = 0; nt < 8; nt++) {
            const int cI = wn * 64 + nt * 8 + 2 * lr;
            float v0 = acc[mt][nt][0] * alpha;
            float v1 = acc[mt][nt][1] * alpha;
            float v2 = acc[mt][nt][2] * alpha;
            float v3 = acc[mt][nt][3] * alpha;
            if (EPI == 2) {
                v0 = __expf(v0 - 6.0f); v1 = __expf(v1 - 6.0f);
                v2 = __expf(v2 - 6.0f); v3 = __expf(v3 - 6.0f);
            }
            *(float2*)&stg[(r    ) * 132 + cI] = make_float2(v0, v1);
            *(float2*)&stg[(r + 8) * 132 + cI] = make_float2(v2, v3);
        }
    }
    __syncthreads();

    if (EPI == 2) {
        const int row  = tid >> 1;
        const int half = tid & 1;
        float sum = 0.0f;
#pragma unroll
        for (int j4 = 0; j4 < 16; j4++) {
            float4 v = *(const float4*)&stg[row * 132 + half * 64 + j4 * 4];
            sum += v.x + v.y + v.z + v.w;
        }
        sum += __shfl_xor_sync(0xFFFFFFFFu, sum, 1);
        if (half == 0)
            partial[(size_t)(z * 16 + blockIdx.x) * Lc + m0 + row] = sum;
    }

    float4 bv = make_float4(0.f, 0.f, 0.f, 0.f);
    if (EPI == 1) bv = *(const float4*)&bias[n0 + lane * 4];
#pragma unroll
    for (int it = 0; it < 16; it++) {
        const int r2 = it * 8 + wid;
        float4 v = *(const float4*)&stg[r2 * 132 + lane * 4];
        if (EPI == 1) { v.x += bv.x; v.y += bv.y; v.z += bv.z; v.w += bv.w; }
        if (EPI == 0) {
            *(float4*)&C[(size_t)(m0 + r2) * ldc + n0 + lane * 4] = v;
        } else {
            __half2 h0 = __floats2half2_rn(v.x, v.y);
            __half2 h1 = __floats2half2_rn(v.z, v.w);
            uint2 u;
            u.x = *(uint32_t*)&h0; u.y = *(uint32_t*)&h1;
            *(uint2*)&C[(size_t)(m0 + r2) * ldc + n0 + lane * 4] = u;
        }
    }
}

// ---------------------------------------------------------------------------
// fp32 -> fp16 elementwise (8 per thread)
// ---------------------------------------------------------------------------
__global__ __launch_bounds__(256)
void conv_h_kernel(const float* __restrict__ src, __half* __restrict__ dst)
{
    const size_t i = ((size_t)blockIdx.x * 256 + threadIdx.x) * 8;
    float4 a = *(const float4*)&src[i];
    float4 b = *(const float4*)&src[i + 4];
    __half2 h0 = __floats2half2_rn(a.x, a.y);
    __half2 h1 = __floats2half2_rn(a.z, a.w);
    __half2 h2 = __floats2half2_rn(b.x, b.y);
    __half2 h3 = __floats2half2_rn(b.z, b.w);
    uint4 u;
    u.x = *(uint32_t*)&h0; u.y = *(uint32_t*)&h1;
    u.z = *(uint32_t*)&h2; u.w = *(uint32_t*)&h3;
    *(uint4*)&dst[i] = u;
}

// x [B,L,D] -> xT [B,D,L] fp16
__global__ __launch_bounds__(256)
void transpose_h_kernel(const float* __restrict__ x, __half* __restrict__ xT)
{
    __shared__ float t[32][33];
    const int b  = blockIdx.z;
    const int l0 = blockIdx.y * 32;
    const int d0 = blockIdx.x * 32;
    const int tx = threadIdx.x, ty = threadIdx.y;
#pragma unroll
    for (int j = 0; j < 4; j++)
        t[ty + 8 * j][tx] = x[(size_t)b * Lc * Dc + (size_t)(l0 + ty + 8 * j) * Dc + d0 + tx];
    __syncthreads();
#pragma unroll
    for (int j = 0; j < 4; j++)
        xT[(size_t)b * Dc * Lc + (size_t)(d0 + ty + 8 * j) * Lc + l0 + tx] =
            __float2half_rn(t[tx][ty + 8 * j]);
}

// gs[z][q] = sum over 16 n-tiles of partial sums
__global__ __launch_bounds__(256)
void reduce_gs_kernel(const float* __restrict__ partial, float* __restrict__ gs)
{
    const int i = blockIdx.x * 256 + threadIdx.x;
    const int z = i >> 11, q = i & (Lc - 1);
    float s = 0.0f;
#pragma unroll
    for (int kt = 0; kt < 16; kt++)
        s += partial[(size_t)(z * 16 + kt) * Lc + q];
    gs[i] = s;
}

// ---------------------------------------------------------------------------
// Per (b,q): head-mean of exp-scores (fp16), decay, renormalize.
// Writes fp32 attn (output) and fp16 attn (K5 operand).
// ---------------------------------------------------------------------------
__global__ __launch_bounds__(256)
void attn_kernel(const __half* __restrict__ E, const float* __restrict__ gs,
                 const float* __restrict__ td, float* __restrict__ attn,
                 __half* __restrict__ attnH)
{
    const int bq = blockIdx.x;            // 0..4095
    const int b  = bq >> 11;
    const int q  = bq & (Lc - 1);
    const int tid = threadIdx.x;

    __shared__ float ish[Hc];
    __shared__ float red[8];

    if (tid < Hc)
        ish[tid] = 1.0f / (16.0f * gs[(b * Hc + tid) * Lc + q]);
    __syncthreads();

    float acc[8];
#pragma unroll
    for (int j = 0; j < 8; j++) acc[j] = 0.0f;

#pragma unroll
    for (int h = 0; h < Hc; h++) {
        const uint4 u = *(const uint4*)&E[((size_t)(b * Hc + h) * Lc + q) * Lc + 8 * tid];
        const float is = ish[h];
        float2 f0 = __half22float2(*(const __half2*)&u.x);
        float2 f1 = __half22float2(*(const __half2*)&u.y);
        float2 f2 = __half22float2(*(const __half2*)&u.z);
        float2 f3 = __half22float2(*(const __half2*)&u.w);
        acc[0] += f0.x * is; acc[1] += f0.y * is;
        acc[2] += f1.x * is; acc[3] += f1.y * is;
        acc[4] += f2.x * is; acc[5] += f2.y * is;
        acc[6] += f3.x * is; acc[7] += f3.y * is;
    }

    const float4 t0 = *(const float4*)&td[(size_t)bq * Lc + 8 * tid];
    const float4 t1 = *(const float4*)&td[(size_t)bq * Lc + 8 * tid + 4];
    float w[8];
    w[0] = acc[0] * __expf(-0.1f * t0.x);
    w[1] = acc[1] * __expf(-0.1f * t0.y);
    w[2] = acc[2] * __expf(-0.1f * t0.z);
    w[3] = acc[3] * __expf(-0.1f * t0.w);
    w[4] = acc[4] * __expf(-0.1f * t1.x);
    w[5] = acc[5] * __expf(-0.1f * t1.y);
    w[6] = acc[6] * __expf(-0.1f * t1.z);
    w[7] = acc[7] * __expf(-0.1f * t1.w);

    float lsum = 0.0f;
#pragma unroll
    for (int j = 0; j < 8; j++) lsum += w[j];
#pragma unroll
    for (int o = 16; o; o >>= 1) lsum += __shfl_xor_sync(0xFFFFFFFFu, lsum, o);
    if ((tid & 31) == 0) red[tid >> 5] = lsum;
    __syncthreads();
    if (tid == 0) {
        float t = 0.0f;
#pragma unroll
        for (int i = 0; i < 8; i++) t += red[i];
        red[0] = 1.0f / (t + 1e-8f);
    }
    __syncthreads();
    const float inv = red[0];

    float o[8];
#pragma unroll
    for (int j = 0; j < 8; j++) o[j] = w[j] * inv;
    *(float4*)&attn[(size_t)bq * Lc + 8 * tid]     = make_float4(o[0], o[1], o[2], o[3]);
    *(float4*)&attn[(size_t)bq * Lc + 8 * tid + 4] = make_float4(o[4], o[5], o[6], o[7]);

    __half2 h0 = __floats2half2_rn(o[0], o[1]);
    __half2 h1 = __floats2half2_rn(o[2], o[3]);
    __half2 h2 = __floats2half2_rn(o[4], o[5]);
    __half2 h3 = __floats2half2_rn(o[6], o[7]);
    uint4 u;
    u.x = *(uint32_t*)&h0; u.y = *(uint32_t*)&h1;
    u.z = *(uint32_t*)&h2; u.w = *(uint32_t*)&h3;
    *(uint4*)&attnH[(size_t)bq * Lc + 8 * tid] = u;
}

// ---------------------------------------------------------------------------
extern "C" void kernel_launch(void* const* d_in, const int* in_sizes, int n_in,
                              void* d_out, int out_size)
{
    const float* x    = (const float*)d_in[0];   // [B,L,D]
    const float* td   = (const float*)d_in[1];   // [B,L,L]
    const float* W    = (const float*)d_in[2];   // [3D,D]
    const float* bias = (const float*)d_in[3];   // [3D]
    float* out = (float*)d_out;

    __half *qk, *S, *xh, *Wh, *xTh, *atnH;
    float *part, *gs, *attn_scratch;
    cudaGetSymbolAddress((void**)&qk, g_qk);
    cudaGetSymbolAddress((void**)&S, g_S);
    cudaGetSymbolAddress((void**)&xh, g_xh);
    cudaGetSymbolAddress((void**)&Wh, g_Wh);
    cudaGetSymbolAddress((void**)&xTh, g_xTh);
    cudaGetSymbolAddress((void**)&atnH, g_atnH);
    cudaGetSymbolAddress((void**)&part, g_part);
    cudaGetSymbolAddress((void**)&gs, g_gs);
    cudaGetSymbolAddress((void**)&attn_scratch, g_attn);

    cudaFuncSetAttribute(gemm_h<0, float>,  cudaFuncAttributeMaxDynamicSharedMemorySize, SMEM_GEMM_BYTES);
    cudaFuncSetAttribute(gemm_h<1, __half>, cudaFuncAttributeMaxDynamicSharedMemorySize, SMEM_GEMM_BYTES);
    cudaFuncSetAttribute(gemm_h<2, __half>, cudaFuncAttributeMaxDynamicSharedMemorySize, SMEM_GEMM_BYTES);

    const long outElems  = (long)Bc * Lc * Dc;   // 4,194,304
    const long attnElems = (long)Bc * Lc * Lc;   // 8,388,608
    float* out_o = out;
    float* out_a = ((long)out_size >= outElems + attnElems) ? (out + outElems)
                                                            : attn_scratch;

    // Prep: fp16 copies of x, W[:2048]; fp16 x^T
    conv_h_kernel<<<(Bc * Lc * Dc) / 2048, 256>>>(x, xh);
    conv_h_kernel<<<(2 * Dc * Dc) / 2048, 256>>>(W, Wh);
    {
        dim3 grid(Dc / 32, Lc / 32, Bc);
        transpose_h_kernel<<<grid, dim3(32, 8)>>>(x, xTh);
    }

    // K1: qk = fp16(xh @ Wh^T + bias)
    {
        dim3 grid(2 * Dc / 128, (Bc * Lc) / 128, 1);
        gemm_h<1, __half><<<grid, 256, SMEM_GEMM_BYTES>>>(
            xh, Dc, 0, 0,
            Wh, Dc, 0, 0,
            qk, 2 * Dc, 0, 0,
            1, Dc, 1.0f, bias, nullptr);
    }

    // K2: S[b,h] = fp16(exp(0.125*Q@K^T - 6)), fused per-row partial sums
    {
        dim3 grid(Lc / 128, Lc / 128, Bc * Hc);
        gemm_h<2, __half><<<grid, 256, SMEM_GEMM_BYTES>>>(
            qk,       2 * Dc, (long)Lc * 2 * Dc, 64,
            qk + Dc,  2 * Dc, (long)Lc * 2 * Dc, 64,
            S,        Lc,     (long)Hc * Lc * Lc, (long)Lc * Lc,
            Hc, 64, 0.125f, nullptr, part);
    }

    // K3: gs = sum of partials
    reduce_gs_kernel<<<(Bc * Hc * Lc) / 256, 256>>>(part, gs);

    // K4: head-mean + decay + renormalize -> attn fp32 + fp16
    attn_kernel<<<Bc * Lc, 256>>>(S, gs, td, out_a, atnH);

    // K5: output = attnH @ xTh^T  (both fp16, K=2048)
    {
        dim3 grid(Dc / 128, Lc / 128, Bc);
        gemm_h<0, float><<<grid, 256, SMEM_GEMM_BYTES>>>(
            atnH, Lc, (long)Lc * Lc, 0,
            xTh,  Lc, (long)Dc * Lc, 0,
            out_o, Dc, (long)Lc * Dc, 0,
            1, Lc, 1.0f, nullptr, nullptr);
    }
}